// round 10
// baseline (speedup 1.0000x reference)
#include <cuda_runtime.h>
#include <cstdint>

// Problem constants (fixed by reference setup_inputs).
constexpr int N_MOLS      = 2000;
constexpr int N_PER_MOL   = 64;
constexpr int PAIRS_PER_M = N_PER_MOL * (N_PER_MOL - 1);   // 4032
constexpr int HALF_PAIRS  = PAIRS_PER_M / 2;               // 2016 (2 pairs/thread)
constexpr int GRID        = 1184;                          // 148 SMs x 8 blocks
constexpr float CUT2      = 25.0f;                         // 5.0^2

// Output layout (flatten of reference tuple, all float32):
//   [0,    P)  : i_idx
//   [P,   2P)  : j_idx
//   [2P,  3P)  : d_ij
//   [3P,  6P)  : r_ij (row-major [P,3])
// with P = N_MOLS * PAIRS_PER_M = 8,064,000.

__global__ __launch_bounds__(256, 8)
void neighborlist_kernel(const float* __restrict__ pos, float* __restrict__ out)
{
    __shared__ float sx[N_PER_MOL];
    __shared__ float sy[N_PER_MOL];
    __shared__ float sz[N_PER_MOL];

    const int t = threadIdx.x;

    const unsigned P = (unsigned)N_MOLS * PAIRS_PER_M;
    float* __restrict__ out_i = out;
    float* __restrict__ out_j = out + P;
    float* __restrict__ out_d = out + 2u * P;
    float* __restrict__ out_r = out + 3u * P;

    // Initial pair decode for c = t (same for every molecule this thread does).
    const int p_init  = 2 * t;
    const int i_init  = p_init / 63;
    const int jr_init = p_init - i_init * 63;

    // Persistent blocks: each block walks molecules bid, bid+1184 (max 2).
    for (int m = blockIdx.x; m < N_MOLS; m += GRID) {
        __syncthreads();   // protect smem reuse across molecules
        if (t < N_PER_MOL) {
            const float* p = pos + (unsigned)(m * N_PER_MOL + t) * 3u;
            sx[t] = p[0];
            sy[t] = p[1];
            sz[t] = p[2];
        }
        __syncthreads();

        const unsigned base   = (unsigned)m * PAIRS_PER_M;
        const float    fabase = (float)(m * N_PER_MOL);

        int i0  = i_init;
        int jr0 = jr_init;

        for (int c = t; c < HALF_PAIRS; c += 256) {
            // pair 1 incrementally from pair 0
            int jr1 = jr0 + 1;
            const int w1 = (jr1 == 63);
            const int i1 = i0 + w1;
            jr1 = w1 ? 0 : jr1;

            const int j0 = jr0 + (jr0 >= i0 ? 1 : 0);
            const int j1 = jr1 + (jr1 >= i1 ? 1 : 0);

            // Pair 0
            const float dx0 = sx[j0] - sx[i0];
            const float dy0 = sy[j0] - sy[i0];
            const float dz0 = sz[j0] - sz[i0];
            const float q0  = fmaf(dx0, dx0, fmaf(dy0, dy0, dz0 * dz0));
            const bool  c0  = (q0 <= CUT2);
            const float d0  = c0 ? sqrtf(q0) : 0.0f;

            // Pair 1
            const float dx1 = sx[j1] - sx[i1];
            const float dy1 = sy[j1] - sy[i1];
            const float dz1 = sz[j1] - sz[i1];
            const float q1  = fmaf(dx1, dx1, fmaf(dy1, dy1, dz1 * dz1));
            const bool  c1  = (q1 <= CUT2);
            const float d1  = c1 ? sqrtf(q1) : 0.0f;

            const unsigned g = base + (unsigned)(2 * c);   // even -> 8B aligned

            *(float2*)(out_i + g) = make_float2(fabase + (float)i0, fabase + (float)i1);
            *(float2*)(out_j + g) = make_float2(fabase + (float)j0, fabase + (float)j1);
            *(float2*)(out_d + g) = make_float2(d0, d1);

            float* __restrict__ r = out_r + 3u * g;        // 3*even -> 8B aligned
            *(float2*)(r + 0) = make_float2(c0 ? dx0 : 0.0f, c0 ? dy0 : 0.0f);
            *(float2*)(r + 2) = make_float2(c0 ? dz0 : 0.0f, c1 ? dx1 : 0.0f);
            *(float2*)(r + 4) = make_float2(c1 ? dy1 : 0.0f, c1 ? dz1 : 0.0f);

            // Advance (i0, jr0) by 512 pairs: 512 = 8*63 + 8 (single wrap max).
            jr0 += 8;
            const int w = (jr0 >= 63);
            jr0 -= w ? 63 : 0;
            i0  += 8 + w;
        }
    }
}

extern "C" void kernel_launch(void* const* d_in, const int* in_sizes, int n_in,
                              void* d_out, int out_size)
{
    const float* pos = (const float*)d_in[0];
    float* out = (float*)d_out;
    neighborlist_kernel<<<GRID, 256>>>(pos, out);
}

// round 11
// speedup vs baseline: 1.1054x; 1.1054x over previous
#include <cuda_runtime.h>
#include <cstdint>

// Problem constants (fixed by reference setup_inputs).
constexpr int N_MOLS      = 2000;
constexpr int N_PER_MOL   = 64;
constexpr int PAIRS_PER_M = N_PER_MOL * (N_PER_MOL - 1);   // 4032
constexpr float CUT2      = 25.0f;                         // 5.0^2

// Output layout (flatten of reference tuple, all float32):
//   [0,    P)  : i_idx
//   [P,   2P)  : j_idx
//   [2P,  3P)  : d_ij
//   [3P,  6P)  : r_ij (row-major [P,3])
// with P = N_MOLS * PAIRS_PER_M = 8,064,000.

__global__ __launch_bounds__(256)
void neighborlist_kernel(const float* __restrict__ pos, float* __restrict__ out)
{
    __shared__ float sx[N_PER_MOL];
    __shared__ float sy[N_PER_MOL];
    __shared__ float sz[N_PER_MOL];

    const int m = blockIdx.x;
    const int t = threadIdx.x;

    if (t < N_PER_MOL) {
        const float* p = pos + (unsigned)(m * N_PER_MOL + t) * 3u;
        sx[t] = p[0];
        sy[t] = p[1];
        sz[t] = p[2];
    }
    __syncthreads();

    const unsigned P = (unsigned)N_MOLS * PAIRS_PER_M;
    float* __restrict__ out_i = out;
    float* __restrict__ out_j = out + P;
    float* __restrict__ out_d = out + 2u * P;
    float* __restrict__ out_r = out + 3u * P;

    const unsigned base   = (unsigned)m * PAIRS_PER_M;
    const float    fabase = (float)(m * N_PER_MOL);

    // Decode thread's first pair once; then advance incrementally by 256
    // pairs per iteration (256 = 4*63 + 4 -> at most one wrap per step).
    int i  = t / 63;
    int jr = t - i * 63;

    for (int p = t; p < PAIRS_PER_M; p += 256) {
        const int j = jr + (jr >= i ? 1 : 0);

        const float dx = sx[j] - sx[i];
        const float dy = sy[j] - sy[i];
        const float dz = sz[j] - sz[i];
        const float q  = fmaf(dx, dx, fmaf(dy, dy, dz * dz));
        const bool  in_cut = (q <= CUT2);

        const unsigned g = base + (unsigned)p;
        out_i[g] = fabase + (float)i;
        out_j[g] = fabase + (float)j;
        out_d[g] = in_cut ? sqrtf(q) : 0.0f;

        float* __restrict__ r = out_r + 3u * g;
        r[0] = in_cut ? dx : 0.0f;
        r[1] = in_cut ? dy : 0.0f;
        r[2] = in_cut ? dz : 0.0f;

        // Advance (i, jr) by 256 pairs: 256 = 4*63 + 4.
        jr += 4;
        const int w = (jr >= 63);
        jr -= w ? 63 : 0;
        i  += 4 + w;
    }
}

extern "C" void kernel_launch(void* const* d_in, const int* in_sizes, int n_in,
                              void* d_out, int out_size)
{
    const float* pos = (const float*)d_in[0];
    float* out = (float*)d_out;
    neighborlist_kernel<<<N_MOLS, 256>>>(pos, out);
}

// round 12
// speedup vs baseline: 1.1617x; 1.0509x over previous
#include <cuda_runtime.h>
#include <cstdint>

// Problem constants (fixed by reference setup_inputs).
constexpr int N_MOLS      = 2000;
constexpr int N_PER_MOL   = 64;
constexpr int PAIRS_PER_M = N_PER_MOL * (N_PER_MOL - 1);   // 4032
constexpr float CUT2      = 25.0f;                         // 5.0^2

// Output layout (flatten of reference tuple, all float32):
//   [0,    P)  : i_idx
//   [P,   2P)  : j_idx
//   [2P,  3P)  : d_ij
//   [3P,  6P)  : r_ij (row-major [P,3])
// with P = N_MOLS * PAIRS_PER_M = 8,064,000.

__global__ __launch_bounds__(256)
void neighborlist_kernel(const float* __restrict__ pos, float* __restrict__ out)
{
    __shared__ float sx[N_PER_MOL];
    __shared__ float sy[N_PER_MOL];
    __shared__ float sz[N_PER_MOL];

    const int m = blockIdx.x;
    const int t = threadIdx.x;

    if (t < N_PER_MOL) {
        const float* p = pos + (unsigned)(m * N_PER_MOL + t) * 3u;
        sx[t] = p[0];
        sy[t] = p[1];
        sz[t] = p[2];
    }
    __syncthreads();

    const unsigned P = (unsigned)N_MOLS * PAIRS_PER_M;
    float* __restrict__ out_i = out;
    float* __restrict__ out_j = out + P;
    float* __restrict__ out_d = out + 2u * P;
    float* __restrict__ out_r = out + 3u * P;

    const unsigned base   = (unsigned)m * PAIRS_PER_M;
    const float    fabase = (float)(m * N_PER_MOL);

    // Decode thread's first pair once; then advance incrementally by 256
    // pairs per iteration (256 = 4*63 + 4 -> at most one wrap per step).
    int i  = t / 63;
    int jr = t - i * 63;

    for (int p = t; p < PAIRS_PER_M; p += 256) {
        const int j = jr + (jr >= i ? 1 : 0);

        const float dx = sx[j] - sx[i];
        const float dy = sy[j] - sy[i];
        const float dz = sz[j] - sz[i];
        const float q  = fmaf(dx, dx, fmaf(dy, dy, dz * dz));
        const bool  in_cut = (q <= CUT2);

        const unsigned g = base + (unsigned)p;

        // Streaming (evict-first) stores: output is write-once, never read,
        // and larger than L2 -- keep it from thrashing the cache.
        __stcs(out_i + g, fabase + (float)i);
        __stcs(out_j + g, fabase + (float)j);
        __stcs(out_d + g, in_cut ? sqrtf(q) : 0.0f);

        float* __restrict__ r = out_r + 3u * g;
        __stcs(r + 0, in_cut ? dx : 0.0f);
        __stcs(r + 1, in_cut ? dy : 0.0f);
        __stcs(r + 2, in_cut ? dz : 0.0f);

        // Advance (i, jr) by 256 pairs: 256 = 4*63 + 4.
        jr += 4;
        const int w = (jr >= 63);
        jr -= w ? 63 : 0;
        i  += 4 + w;
    }
}

extern "C" void kernel_launch(void* const* d_in, const int* in_sizes, int n_in,
                              void* d_out, int out_size)
{
    const float* pos = (const float*)d_in[0];
    float* out = (float*)d_out;
    neighborlist_kernel<<<N_MOLS, 256>>>(pos, out);
}